// round 13
// baseline (speedup 1.0000x reference)
#include <cuda_runtime.h>
#include <math.h>

#define Bn   2048
#define Hn   64
#define An   32
#define Sn   32
#define Dn   200
#define OUTC 296
#define BT   16
#define NT   512

#define SR4  416   // padded stride for NOUT=400->416
#define SR2  224   // padded stride for NOUT=200->208

// ---------- persistent transposed weights (device globals, zero-padded) ----------
__device__ float g_Wru[272 * SR4];   // [K=272][416] fused r,u over [x;h]
__device__ float g_bru[416];
__device__ float g_Win[64 * SR2];    // i_n over x
__device__ float g_bin[208];
__device__ float g_Whn[208 * SR2];   // h_n over h
__device__ float g_bhn[208];
__device__ float g_W1t[208 * SR2];
__device__ float g_b1s[208];
__device__ float g_W2t[208 * SR2];
__device__ float g_b2s[208];
__device__ float g_Wms[208 * 64];    // heads: cols 0..31 mean, 32..63 logstd
__device__ float g_bms[64];

// ---------- packed fp32x2 helpers ----------
__device__ __forceinline__ unsigned long long fma2_(unsigned long long a,
                                                    unsigned long long b,
                                                    unsigned long long c) {
    unsigned long long d;
    asm("fma.rn.f32x2 %0, %1, %2, %3;" : "=l"(d) : "l"(a), "l"(b), "l"(c));
    return d;
}
__device__ __forceinline__ unsigned long long splat2_(float w) {
    unsigned long long d;
    asm("mov.b64 %0, {%1, %1};" : "=l"(d) : "f"(w));
    return d;
}
__device__ __forceinline__ void unpack2_(unsigned long long v, float& lo, float& hi) {
    asm("mov.b64 {%0, %1}, %2;" : "=f"(lo), "=f"(hi) : "l"(v));
}
__device__ __forceinline__ float sigf_(float x) { return 1.0f / (1.0f + __expf(-x)); }

// ---------- weight transpose / fuse (every launch; deterministic) ----------
__global__ void rssm_preproc(
    const float* __restrict__ W_ih, const float* __restrict__ b_ih,
    const float* __restrict__ W_hh, const float* __restrict__ b_hh,
    const float* __restrict__ W1,   const float* __restrict__ b1,
    const float* __restrict__ W2,   const float* __restrict__ b2,
    const float* __restrict__ Wm,   const float* __restrict__ bm,
    const float* __restrict__ Ws,   const float* __restrict__ bs)
{
    int i0 = blockIdx.x * blockDim.x + threadIdx.x;
    int stride = gridDim.x * blockDim.x;

    for (int idx = i0; idx < 272 * SR4; idx += stride) {
        int k = idx / SR4, o = idx % SR4;
        float v = 0.0f;
        if (o < 400) {
            if (k < 64) v = W_ih[o * 64 + k];
            else if (k < 264) v = W_hh[o * 200 + (k - 64)];
        }
        g_Wru[idx] = v;
    }
    for (int idx = i0; idx < 416; idx += stride)
        g_bru[idx] = (idx < 400) ? (b_ih[idx] + b_hh[idx]) : 0.0f;

    for (int idx = i0; idx < 64 * SR2; idx += stride) {
        int k = idx / SR2, o = idx % SR2;
        g_Win[idx] = (o < 200) ? W_ih[(400 + o) * 64 + k] : 0.0f;
    }
    for (int idx = i0; idx < 208; idx += stride)
        g_bin[idx] = (idx < 200) ? b_ih[400 + idx] : 0.0f;

    for (int idx = i0; idx < 208 * SR2; idx += stride) {
        int k = idx / SR2, o = idx % SR2;
        bool live = (k < 200) && (o < 200);
        g_Whn[idx] = live ? W_hh[(400 + o) * 200 + k] : 0.0f;
        g_W1t[idx] = live ? W1[o * 200 + k] : 0.0f;
        g_W2t[idx] = live ? W2[o * 200 + k] : 0.0f;
    }
    for (int idx = i0; idx < 208; idx += stride) {
        bool live = (idx < 200);
        g_bhn[idx] = live ? b_hh[400 + idx] : 0.0f;
        g_b1s[idx] = live ? b1[idx] : 0.0f;
        g_b2s[idx] = live ? b2[idx] : 0.0f;
    }

    for (int idx = i0; idx < 208 * 64; idx += stride) {
        int k = idx / 64, o = idx % 64;
        float v = 0.0f;
        if (k < 200) v = (o < 32) ? Wm[o * 200 + k] : Ws[(o - 32) * 200 + k];
        g_Wms[idx] = v;
    }
    for (int idx = i0; idx < 64; idx += stride)
        g_bms[idx] = (idx < 32) ? bm[idx] : bs[idx - 32];
}

// ---------- gemm2w: C=2 cols x 8 rows (RG=2), LDG.64 weights, depth-8 prefetch ----
// threads used: NOUT (one per col-pair x row-group). K % 16 == 0. ACT: 1=sigmoid.
template<int K, int SR, int ACT>
__device__ __forceinline__ void gemm2w(const float* __restrict__ Wt,
                                       const float* __restrict__ bias,
                                       const float* __restrict__ xT,
                                       float* __restrict__ outT, int t)
{
    const int cg = t >> 1, rg = t & 1;
    const float* wp = Wt + cg * 2;
    const float* xb = xT + rg * 8;

    unsigned long long acc[2][4];
#pragma unroll
    for (int ci = 0; ci < 2; ci++)
#pragma unroll
        for (int q = 0; q < 4; q++) acc[ci][q] = 0ull;

    auto LD = [&](float2* b, int k0) {
#pragma unroll
        for (int p = 0; p < 8; p++)
            b[p] = __ldg(reinterpret_cast<const float2*>(wp + (size_t)(k0 + p) * SR));
    };
    auto CP = [&](const float2* b, int k0) {
#pragma unroll
        for (int p = 0; p < 8; p++) {
            int k = k0 + p;
            ulonglong2 xa = *reinterpret_cast<const ulonglong2*>(xb + k * BT);
            ulonglong2 xc = *reinterpret_cast<const ulonglong2*>(xb + k * BT + 4);
            unsigned long long w0 = splat2_(b[p].x), w1 = splat2_(b[p].y);
            acc[0][0] = fma2_(w0, xa.x, acc[0][0]);
            acc[0][1] = fma2_(w0, xa.y, acc[0][1]);
            acc[0][2] = fma2_(w0, xc.x, acc[0][2]);
            acc[0][3] = fma2_(w0, xc.y, acc[0][3]);
            acc[1][0] = fma2_(w1, xa.x, acc[1][0]);
            acc[1][1] = fma2_(w1, xa.y, acc[1][1]);
            acc[1][2] = fma2_(w1, xc.x, acc[1][2]);
            acc[1][3] = fma2_(w1, xc.y, acc[1][3]);
        }
    };

    float2 bufA[8], bufB[8];
    LD(bufA, 0);
    for (int k0 = 0; k0 < K; k0 += 16) {
        LD(bufB, k0 + 8);
        CP(bufA, k0);
        if (k0 + 16 < K) LD(bufA, k0 + 16);
        CP(bufB, k0 + 8);
    }

#pragma unroll
    for (int ci = 0; ci < 2; ci++) {
        int c = cg * 2 + ci;
        float bv = bias[c];
#pragma unroll
        for (int q = 0; q < 4; q++) {
            float lo, hi; unpack2_(acc[ci][q], lo, hi);
            lo += bv; hi += bv;
            if (ACT == 1) { lo = sigf_(lo); hi = sigf_(hi); }
            outT[c * BT + rg * 8 + 2 * q]     = lo;
            outT[c * BT + rg * 8 + 2 * q + 1] = hi;
        }
    }
}

// ---------- gemm1: C=1 col x 8 rows (RG=2), LDG.32 weights, depth-8 prefetch ----
// threads used: 2*NOUT. K % 16 == 0. ACT: 0=none, 2=elu.
template<int K, int SR, int ACT>
__device__ __forceinline__ void gemm1(const float* __restrict__ Wt,
                                      const float* __restrict__ bias,
                                      const float* __restrict__ xT,
                                      float* __restrict__ outT, int t)
{
    const int c = t >> 1, rg = t & 1;
    const float* wp = Wt + c;
    const float* xb = xT + rg * 8;

    unsigned long long acc[4];
#pragma unroll
    for (int q = 0; q < 4; q++) acc[q] = 0ull;

    auto LD = [&](float* b, int k0) {
#pragma unroll
        for (int p = 0; p < 8; p++)
            b[p] = __ldg(wp + (size_t)(k0 + p) * SR);
    };
    auto CP = [&](const float* b, int k0) {
#pragma unroll
        for (int p = 0; p < 8; p++) {
            int k = k0 + p;
            ulonglong2 xa = *reinterpret_cast<const ulonglong2*>(xb + k * BT);
            ulonglong2 xc = *reinterpret_cast<const ulonglong2*>(xb + k * BT + 4);
            unsigned long long w0 = splat2_(b[p]);
            acc[0] = fma2_(w0, xa.x, acc[0]);
            acc[1] = fma2_(w0, xa.y, acc[1]);
            acc[2] = fma2_(w0, xc.x, acc[2]);
            acc[3] = fma2_(w0, xc.y, acc[3]);
        }
    };

    float bufA[8], bufB[8];
    LD(bufA, 0);
    for (int k0 = 0; k0 < K; k0 += 16) {
        LD(bufB, k0 + 8);
        CP(bufA, k0);
        if (k0 + 16 < K) LD(bufA, k0 + 16);
        CP(bufB, k0 + 8);
    }

    float bv = bias[c];
#pragma unroll
    for (int q = 0; q < 4; q++) {
        float lo, hi; unpack2_(acc[q], lo, hi);
        lo += bv; hi += bv;
        if (ACT == 2) {
            lo = lo > 0.0f ? lo : (__expf(lo) - 1.0f);
            hi = hi > 0.0f ? hi : (__expf(hi) - 1.0f);
        }
        outT[c * BT + rg * 8 + 2 * q]     = lo;
        outT[c * BT + rg * 8 + 2 * q + 1] = hi;
    }
}

// ---------- main rollout kernel: 1 CTA = 16 batch rows, all 64 steps ----------
extern __shared__ float smf[];

// SMEM float offsets
#define OXH  0                   // [272][16]: z 0..31, a 32..63, h 64..263, pad
#define OEP  (OXH + 272*16)      // 2 x [32][16] double-buffered eps
#define ORU  (OEP + 2*32*16)     // [416][16] sigmoid(r,u) incl pad cols
#define OHP  (ORU + 416*16)      // [8][64][16] head partials
#define OMS  (OHP + 8*64*16)     // [64][16] mean(0..31), std(32..63)
#define ONB1 (OMS + 64*16)       // [208][16] i_n -> f1
#define ONB2 (ONB1 + 208*16)     // [208][16] h_n -> f2
#define SMEMF (ONB2 + 208*16)
#define SMEMB (SMEMF * 4)

__global__ void __launch_bounds__(NT, 1) rssm_main(
    const float* __restrict__ h0, const float* __restrict__ z0,
    const float* __restrict__ actions, const float* __restrict__ eps,
    float* __restrict__ out)
{
    float* xh  = smf + OXH;
    float* ep  = smf + OEP;   // ep + (t&1)*512
    float* ru  = smf + ORU;
    float* hp  = smf + OHP;
    float* ms  = smf + OMS;
    float* nb1 = smf + ONB1;
    float* nb2 = smf + ONB2;

    const int tid = threadIdx.x;
    const int b0  = blockIdx.x * BT;

    // emit step tq (reads xh-h, xh-z, ms; all stable during next step's phase A)
    auto emit_step = [&](int tq, int i0, int istep) {
        for (int idx = i0; idx < OUTC * BT; idx += istep) {
            int r = idx / OUTC, c = idx - r * OUTC;
            float v;
            if (c < 200)      v = xh[64 * BT + c * BT + r];
            else if (c < 232) v = xh[(c - 200) * BT + r];
            else              v = ms[(c - 232) * BT + r];
            out[((size_t)(b0 + r) * Hn + tq) * OUTC + c] = v;
        }
    };
    // stage actions[tq] into xh-a and eps[tq] into ep buffer (tq&1)
    auto stage = [&](int tq, int i0, int istep) {
        float* epb = ep + (tq & 1) * 512;
        for (int idx = i0; idx < An * BT; idx += istep) {
            int r = idx >> 5, c = idx & 31;
            size_t gbase = ((size_t)(b0 + r) * Hn + tq);
            xh[(32 + c) * BT + r] = actions[gbase * An + c];
            epb[c * BT + r]       = eps[gbase * Sn + c];
        }
    };

    // initial state + zero K-pad rows
    for (int idx = tid; idx < Dn * BT; idx += NT) {
        int f = idx >> 4, r = idx & 15;
        xh[64 * BT + idx] = h0[(b0 + r) * Dn + f];
    }
    for (int idx = tid; idx < Sn * BT; idx += NT) {
        int f = idx >> 4, r = idx & 15;
        xh[idx] = z0[(b0 + r) * Sn + f];
    }
    for (int idx = tid; idx < 8 * BT; idx += NT) {
        xh[264 * BT + idx] = 0.0f;
        nb1[200 * BT + idx] = 0.0f;
        nb2[200 * BT + idx] = 0.0f;
    }
    stage(0, tid, NT);
    __syncthreads();

    for (int t = 0; t < Hn; t++) {
        // ---- Phase A: GEMMs on warps 0-12 (tid<416); emit(t-1) on warps 13-15 ----
        if (tid < 416) {
            gemm2w<272, SR4, 1>(g_Wru, g_bru, xh, ru, tid);            // sigmoid(r,u), 416 cols
            gemm1 <208, SR2, 0>(g_Whn, g_bhn, xh + 64 * BT, nb2, tid); // h_n, 208 cols
            gemm1 < 64, SR2, 0>(g_Win, g_bin, xh, nb1, tid);           // i_n, 208 cols
        } else if (t > 0) {
            emit_step(t - 1, tid - 416, NT - 416);
        }
        __syncthreads();

        // ---- Phase B: pointwise GRU update (all threads, in place on h) ----
        for (int idx = tid; idx < Dn * BT; idx += NT) {
            int f = idx >> 4;
            float rr = ru[idx], u = ru[(200 + f) * BT + (idx & 15)];
            float n  = tanhf(nb1[idx] + rr * nb2[idx]);
            float hv = xh[64 * BT + idx];
            xh[64 * BT + idx] = (1.0f - u) * n + u * hv;
        }
        __syncthreads();

        // ---- Phase C: f1 on tid<416; stage(t+1) on warps 13-15 ----
        if (tid < 416)
            gemm1<208, SR2, 2>(g_W1t, g_b1s, xh + 64 * BT, nb1, tid);
        else if (t + 1 < Hn)
            stage(t + 1, tid - 416, NT - 416);
        __syncthreads();

        // ---- Phase D: f2 ----
        if (tid < 416)
            gemm1<208, SR2, 2>(g_W2t, g_b2s, nb1, nb2, tid);
        __syncthreads();

        // ---- Phase E: heads (Nout=64, padded K=208), 8-way K-split of 26 ----
        {
            int o = tid & 63, p = tid >> 6;
            const float* wp = g_Wms + p * 26 * 64 + o;
            const float* xb = nb2 + p * 26 * BT;
            unsigned long long acc[8];
#pragma unroll
            for (int q = 0; q < 8; q++) acc[q] = 0ull;
#pragma unroll
            for (int k = 0; k < 26; k += 2) {
                float w0 = __ldg(wp + k * 64);
                float w1 = __ldg(wp + (k + 1) * 64);
                unsigned long long wd0 = splat2_(w0), wd1 = splat2_(w1);
                const ulonglong2* x0 = reinterpret_cast<const ulonglong2*>(xb + k * BT);
                const ulonglong2* x1 = reinterpret_cast<const ulonglong2*>(xb + (k + 1) * BT);
#pragma unroll
                for (int q = 0; q < 4; q++) {
                    ulonglong2 a = x0[q], b = x1[q];
                    acc[2 * q]     = fma2_(wd0, a.x, acc[2 * q]);
                    acc[2 * q + 1] = fma2_(wd0, a.y, acc[2 * q + 1]);
                    acc[2 * q]     = fma2_(wd1, b.x, acc[2 * q]);
                    acc[2 * q + 1] = fma2_(wd1, b.y, acc[2 * q + 1]);
                }
            }
            float v[16];
#pragma unroll
            for (int q = 0; q < 8; q++) { unpack2_(acc[q], v[2 * q], v[2 * q + 1]); }
            float4* dp = reinterpret_cast<float4*>(hp + p * 1024 + o * BT);
#pragma unroll
            for (int q = 0; q < 4; q++)
                dp[q] = make_float4(v[4 * q], v[4 * q + 1], v[4 * q + 2], v[4 * q + 3]);
        }
        __syncthreads();

        // ---- Phase F: reduce 8 head partials; mean raw, std = exp(clip) ----
        for (int idx = tid; idx < 1024; idx += NT) {
            int o = idx >> 4;
            float v = g_bms[o];
#pragma unroll
            for (int p = 0; p < 8; p++) v += hp[p * 1024 + idx];
            if (o < 32) ms[idx] = v;
            else        ms[idx] = __expf(fminf(fmaxf(v, -10.0f), 2.0f));
        }
        __syncthreads();

        // ---- Phase G: z_new = mean + std*eps ----
        {
            const float* epc = ep + (t & 1) * 512;
            for (int idx = tid; idx < Sn * BT; idx += NT)
                xh[idx] = ms[idx] + ms[512 + idx] * epc[idx];
        }
        __syncthreads();
    }

    // final emit (step Hn-1), all threads
    emit_step(Hn - 1, tid, NT);
}

// ---------- launch ----------
extern "C" void kernel_launch(void* const* d_in, const int* in_sizes, int n_in,
                              void* d_out, int out_size)
{
    const float* h0      = (const float*)d_in[0];
    const float* z0      = (const float*)d_in[1];
    const float* actions = (const float*)d_in[2];
    const float* eps_    = (const float*)d_in[3];
    const float* W_ih = (const float*)d_in[4];  const float* b_ih = (const float*)d_in[5];
    const float* W_hh = (const float*)d_in[6];  const float* b_hh = (const float*)d_in[7];
    const float* W1   = (const float*)d_in[8];  const float* b1   = (const float*)d_in[9];
    const float* W2   = (const float*)d_in[10]; const float* b2   = (const float*)d_in[11];
    const float* Wm   = (const float*)d_in[12]; const float* bm   = (const float*)d_in[13];
    const float* Ws   = (const float*)d_in[14]; const float* bs   = (const float*)d_in[15];
    float* out = (float*)d_out;

    cudaFuncSetAttribute(rssm_main, cudaFuncAttributeMaxDynamicSharedMemorySize, SMEMB);

    rssm_preproc<<<128, 256>>>(W_ih, b_ih, W_hh, b_hh, W1, b1, W2, b2, Wm, bm, Ws, bs);
    rssm_main<<<Bn / BT, NT, SMEMB>>>(h0, z0, actions, eps_, out);
}

// round 15
// speedup vs baseline: 1.0248x; 1.0248x over previous
#include <cuda_runtime.h>
#include <math.h>

#define Bn   2048
#define Hn   64
#define An   32
#define Sn   32
#define Dn   200
#define OUTC 296
#define BT   16
#define NT   512

#define SZ   640   // stride of fused z-GEMM weights [64][640]: ru(416) | i_n(208) | pad
#define SH   576   // stride of fused h-GEMM weights [208][576]: ru_h(416) | hn_head(160)
#define S1   208   // stride of [208][208] matrices

// ---------- persistent transposed weights ----------
__device__ float g_Wz  [64  * SZ];   // z/a part: K=64 over x=[z|a]
__device__ float g_Wruh[208 * SH];   // h part of r,u + hn head: K=208 over h
__device__ float g_WhnT[208 * S1];   // full h_n (tail cols + prologue)
__device__ float g_W1t [208 * S1];
__device__ float g_W2t [208 * S1];
__device__ float g_Wms [208 * 64];
__device__ float g_bru[416];
__device__ float g_bin[208];
__device__ float g_bhn[208];
__device__ float g_b1s[208];
__device__ float g_b2s[208];
__device__ float g_bms[64];

// ---------- packed fp32x2 helpers ----------
__device__ __forceinline__ unsigned long long fma2_(unsigned long long a,
                                                    unsigned long long b,
                                                    unsigned long long c) {
    unsigned long long d;
    asm("fma.rn.f32x2 %0, %1, %2, %3;" : "=l"(d) : "l"(a), "l"(b), "l"(c));
    return d;
}
__device__ __forceinline__ unsigned long long splat2_(float w) {
    unsigned long long d;
    asm("mov.b64 %0, {%1, %1};" : "=l"(d) : "f"(w));
    return d;
}
__device__ __forceinline__ void unpack2_(unsigned long long v, float& lo, float& hi) {
    asm("mov.b64 {%0, %1}, %2;" : "=f"(lo), "=f"(hi) : "l"(v));
}
__device__ __forceinline__ float sigf_(float x) { return 1.0f / (1.0f + __expf(-x)); }
#define YBAR() asm volatile("bar.sync 1, 224;" ::: "memory")

// ---------- weight transpose / fuse ----------
__global__ void rssm_preproc(
    const float* __restrict__ W_ih, const float* __restrict__ b_ih,
    const float* __restrict__ W_hh, const float* __restrict__ b_hh,
    const float* __restrict__ W1,   const float* __restrict__ b1,
    const float* __restrict__ W2,   const float* __restrict__ b2,
    const float* __restrict__ Wm,   const float* __restrict__ bm,
    const float* __restrict__ Ws,   const float* __restrict__ bs)
{
    int i0 = blockIdx.x * blockDim.x + threadIdx.x;
    int stride = gridDim.x * blockDim.x;

    // g_Wz[k][o]: o<400 -> W_ih[o][k] (r,u); 416<=o<624 -> W_ih[400+o-416][k] (i_n)
    for (int idx = i0; idx < 64 * SZ; idx += stride) {
        int k = idx / SZ, o = idx % SZ;
        float v = 0.0f;
        if (o < 400) v = W_ih[o * 64 + k];
        else if (o >= 416 && o < 624) v = W_ih[(400 + o - 416) * 64 + k];
        g_Wz[idx] = v;
    }
    // g_Wruh[k][o]: o<400 -> W_hh[o][k] (r,u over h); 416<=o<576 -> W_hh[400+o-416][k] (hn head)
    for (int idx = i0; idx < 208 * SH; idx += stride) {
        int k = idx / SH, o = idx % SH;
        float v = 0.0f;
        if (k < 200) {
            if (o < 400) v = W_hh[o * 200 + k];
            else if (o >= 416) v = W_hh[(400 + o - 416) * 200 + k];
        }
        g_Wruh[idx] = v;
    }
    for (int idx = i0; idx < 208 * S1; idx += stride) {
        int k = idx / S1, o = idx % S1;
        bool live = (k < 200) && (o < 200);
        g_WhnT[idx] = live ? W_hh[(400 + o) * 200 + k] : 0.0f;
        g_W1t[idx]  = live ? W1[o * 200 + k] : 0.0f;
        g_W2t[idx]  = live ? W2[o * 200 + k] : 0.0f;
    }
    for (int idx = i0; idx < 208 * 64; idx += stride) {
        int k = idx / 64, o = idx % 64;
        float v = 0.0f;
        if (k < 200) v = (o < 32) ? Wm[o * 200 + k] : Ws[(o - 32) * 200 + k];
        g_Wms[idx] = v;
    }
    for (int idx = i0; idx < 416; idx += stride)
        g_bru[idx] = (idx < 400) ? (b_ih[idx] + b_hh[idx]) : 0.0f;
    for (int idx = i0; idx < 208; idx += stride) {
        bool live = (idx < 200);
        g_bin[idx] = live ? b_ih[400 + idx] : 0.0f;
        g_bhn[idx] = live ? b_hh[400 + idx] : 0.0f;
        g_b1s[idx] = live ? b1[idx] : 0.0f;
        g_b2s[idx] = live ? b2[idx] : 0.0f;
    }
    for (int idx = i0; idx < 64; idx += stride)
        g_bms[idx] = (idx < 32) ? bm[idx] : bs[idx - 32];
}

// ---------- gemm_c2: 2 cols x 16 rows per thread, raw output (no bias/act) ----------
// K % 8 == 0. Depth-4 double-buffered LDG.64 weights; broadcast LDS.128 x-reads.
template<int K, int SR>
__device__ __forceinline__ void gemm_c2(const float* __restrict__ Wt,
                                        const float* __restrict__ xT,
                                        float* __restrict__ outT, int cg)
{
    const float* wp = Wt + cg * 2;
    unsigned long long acc[2][8];
#pragma unroll
    for (int ci = 0; ci < 2; ci++)
#pragma unroll
        for (int q = 0; q < 8; q++) acc[ci][q] = 0ull;

    auto LD = [&](float2* b, int k0) {
#pragma unroll
        for (int p = 0; p < 4; p++)
            b[p] = __ldg(reinterpret_cast<const float2*>(wp + (size_t)(k0 + p) * SR));
    };
    auto CP = [&](const float2* b, int k0) {
#pragma unroll
        for (int p = 0; p < 4; p++) {
            int k = k0 + p;
            const ulonglong2* xp = reinterpret_cast<const ulonglong2*>(xT + k * BT);
            ulonglong2 x0 = xp[0], x1 = xp[1], x2 = xp[2], x3 = xp[3];
            unsigned long long w0 = splat2_(b[p].x), w1 = splat2_(b[p].y);
            acc[0][0] = fma2_(w0, x0.x, acc[0][0]);
            acc[0][1] = fma2_(w0, x0.y, acc[0][1]);
            acc[0][2] = fma2_(w0, x1.x, acc[0][2]);
            acc[0][3] = fma2_(w0, x1.y, acc[0][3]);
            acc[0][4] = fma2_(w0, x2.x, acc[0][4]);
            acc[0][5] = fma2_(w0, x2.y, acc[0][5]);
            acc[0][6] = fma2_(w0, x3.x, acc[0][6]);
            acc[0][7] = fma2_(w0, x3.y, acc[0][7]);
            acc[1][0] = fma2_(w1, x0.x, acc[1][0]);
            acc[1][1] = fma2_(w1, x0.y, acc[1][1]);
            acc[1][2] = fma2_(w1, x1.x, acc[1][2]);
            acc[1][3] = fma2_(w1, x1.y, acc[1][3]);
            acc[1][4] = fma2_(w1, x2.x, acc[1][4]);
            acc[1][5] = fma2_(w1, x2.y, acc[1][5]);
            acc[1][6] = fma2_(w1, x3.x, acc[1][6]);
            acc[1][7] = fma2_(w1, x3.y, acc[1][7]);
        }
    };

    float2 bufA[4], bufB[4];
    LD(bufA, 0);
    for (int k0 = 0; k0 < K; k0 += 8) {
        LD(bufB, k0 + 4);
        CP(bufA, k0);
        if (k0 + 8 < K) LD(bufA, k0 + 8);
        CP(bufB, k0 + 4);
    }

#pragma unroll
    for (int ci = 0; ci < 2; ci++) {
        float* op = outT + (cg * 2 + ci) * BT;
#pragma unroll
        for (int q = 0; q < 4; q++) {
            float a0, a1, a2, a3;
            unpack2_(acc[ci][2 * q], a0, a1);
            unpack2_(acc[ci][2 * q + 1], a2, a3);
            reinterpret_cast<float4*>(op)[q] = make_float4(a0, a1, a2, a3);
        }
    }
}

// ---------- gemm_c1: 1 col x 16 rows per thread. ACT: 0=none, 2=elu. BIAS opt. ----
template<int K, int SR, int BIAS, int ACT>
__device__ __forceinline__ void gemm_c1(const float* __restrict__ Wt,
                                        const float* __restrict__ bias,
                                        const float* __restrict__ xT,
                                        float* __restrict__ outT, int c)
{
    const float* wp = Wt + c;
    unsigned long long acc[8];
#pragma unroll
    for (int q = 0; q < 8; q++) acc[q] = 0ull;

    auto LD = [&](float* b, int k0) {
#pragma unroll
        for (int p = 0; p < 8; p++)
            b[p] = __ldg(wp + (size_t)(k0 + p) * SR);
    };
    auto CP = [&](const float* b, int k0) {
#pragma unroll
        for (int p = 0; p < 8; p++) {
            int k = k0 + p;
            const ulonglong2* xp = reinterpret_cast<const ulonglong2*>(xT + k * BT);
            ulonglong2 x0 = xp[0], x1 = xp[1], x2 = xp[2], x3 = xp[3];
            unsigned long long w0 = splat2_(b[p]);
            acc[0] = fma2_(w0, x0.x, acc[0]);
            acc[1] = fma2_(w0, x0.y, acc[1]);
            acc[2] = fma2_(w0, x1.x, acc[2]);
            acc[3] = fma2_(w0, x1.y, acc[3]);
            acc[4] = fma2_(w0, x2.x, acc[4]);
            acc[5] = fma2_(w0, x2.y, acc[5]);
            acc[6] = fma2_(w0, x3.x, acc[6]);
            acc[7] = fma2_(w0, x3.y, acc[7]);
        }
    };

    float bufA[8], bufB[8];
    LD(bufA, 0);
    for (int k0 = 0; k0 < K; k0 += 16) {
        LD(bufB, k0 + 8);
        CP(bufA, k0);
        if (k0 + 16 < K) LD(bufA, k0 + 16);
        CP(bufB, k0 + 8);
    }

    float bv = BIAS ? bias[c] : 0.0f;
    float* op = outT + c * BT;
#pragma unroll
    for (int q = 0; q < 4; q++) {
        float a0, a1, a2, a3;
        unpack2_(acc[2 * q], a0, a1);
        unpack2_(acc[2 * q + 1], a2, a3);
        a0 += bv; a1 += bv; a2 += bv; a3 += bv;
        if (ACT == 2) {
            a0 = a0 > 0.0f ? a0 : (__expf(a0) - 1.0f);
            a1 = a1 > 0.0f ? a1 : (__expf(a1) - 1.0f);
            a2 = a2 > 0.0f ? a2 : (__expf(a2) - 1.0f);
            a3 = a3 > 0.0f ? a3 : (__expf(a3) - 1.0f);
        }
        reinterpret_cast<float4*>(op)[q] = make_float4(a0, a1, a2, a3);
    }
}

// ---------- main rollout kernel ----------
extern __shared__ float smf[];

// SMEM float offsets (all 16B aligned)
#define OXH  0                    // [272][16]: z 0..31, a 32..63, h 64..271 (pad 264..271)
#define OEP  (OXH + 272*16)       // [32][16] eps
#define OGZ  (OEP + 32*16)        // [640][16]: ru_z(416) | i_n(208) | pad
#define ORUP (OGZ + 640*16)       // [624][16]: ruP(416) | hnB(208)
#define OF1  (ORUP + 624*16)      // [208][16]
#define OF2  (OF1 + 208*16)       // [208][16]
#define OHP  (OF2 + 208*16)       // [3][64][16] head partials
#define OMS  (OHP + 3*64*16)      // [64][16] mean/std
#define SMEMF (OMS + 64*16)
#define SMEMB (SMEMF * 4)

__global__ void __launch_bounds__(NT, 1) rssm_main(
    const float* __restrict__ h0, const float* __restrict__ z0,
    const float* __restrict__ actions, const float* __restrict__ eps,
    float* __restrict__ out)
{
    float* xh   = smf + OXH;
    float* ep   = smf + OEP;
    float* gz   = smf + OGZ;
    float* ruPC = smf + ORUP;          // ruP cols 0..415; hnB = cols 416..623
    float* hnB  = ruPC + 416 * BT;
    float* f1   = smf + OF1;
    float* f2   = smf + OF2;
    float* hp   = smf + OHP;
    float* ms   = smf + OMS;

    const int tid = threadIdx.x;
    const int b0  = blockIdx.x * BT;
    float* xhH = xh + 64 * BT;         // h region (K=208 incl pad)

    auto emit_step = [&](int tq, int i0, int istep) {
        for (int idx = i0; idx < OUTC * BT; idx += istep) {
            int r = idx / OUTC, c = idx - r * OUTC;
            float v;
            if (c < 200)      v = xhH[c * BT + r];
            else if (c < 232) v = xh[(c - 200) * BT + r];
            else              v = ms[(c - 232) * BT + r];
            out[((size_t)(b0 + r) * Hn + tq) * OUTC + c] = v;
        }
    };
    auto stage = [&](int tq, int i0, int istep) {
        for (int idx = i0; idx < An * BT; idx += istep) {
            int r = idx >> 5, c = idx & 31;
            size_t gbase = ((size_t)(b0 + r) * Hn + tq);
            xh[(32 + c) * BT + r] = actions[gbase * An + c];
            ep[c * BT + r]        = eps[gbase * Sn + c];
        }
    };

    // ---- prologue: load state, zero pads, stage(0) ----
    for (int idx = tid; idx < Dn * BT; idx += NT) {
        int f = idx >> 4, r = idx & 15;
        xhH[idx] = h0[(b0 + r) * Dn + f];
    }
    for (int idx = tid; idx < Sn * BT; idx += NT) {
        int f = idx >> 4, r = idx & 15;
        xh[idx] = z0[(b0 + r) * Sn + f];
    }
    for (int idx = tid; idx < 8 * BT; idx += NT)
        xhH[200 * BT + idx] = 0.0f;    // h K-pad rows
    stage(0, tid, NT);
    __syncthreads();

    // prologue gates_h: ruP + full hnB from h0
    if (tid < 288)
        gemm_c2<208, SH>(g_Wruh, xhH, ruPC, tid);            // cols 0..575
    else if (tid < 336)
        gemm_c1<208, S1, 0, 0>(g_WhnT, nullptr, xhH, hnB, 160 + (tid - 288)); // hn tail
    __syncthreads();

    for (int t = 0; t < Hn; t++) {
        // ---- P1: fused z-GEMM [ru_z | i_n] on tid<320; hnB tail from h(t-1) ----
        if (tid < 320)
            gemm_c2<64, SZ>(g_Wz, xh, gz, tid);              // K=64 over [z|a]
        else if (tid < 368)
            gemm_c1<208, S1, 0, 0>(g_WhnT, nullptr, xhH, hnB, 160 + (tid - 320));
        __syncthreads();

        // ---- P2: pointwise GRU update (all threads) ----
        for (int idx = tid; idx < Dn * BT; idx += NT) {
            int f = idx >> 4;
            float rr = sigf_(gz[idx] + ruPC[idx] + g_bru[f]);
            float uu = sigf_(gz[3200 + idx] + ruPC[3200 + idx] + g_bru[200 + f]);
            float hn = hnB[idx] + g_bhn[f];
            float nn = tanhf(gz[6656 + idx] + g_bin[f] + rr * hn);
            float hv = xhH[idx];
            xhH[idx] = (1.0f - uu) * nn + uu * hv;
        }
        __syncthreads();

        // ---- P3: X computes next step's h-GEMMs; Y runs MLP chain ----
        if (tid < 288) {
            // X: ruP(t+1) + hnB head (cols 0..159) from h(t)
            gemm_c2<208, SH>(g_Wruh, xhH, ruPC, tid);
        } else {
            int ty = tid - 288;   // 0..223
            if (ty < 208)
                gemm_c1<208, S1, 1, 2>(g_W1t, g_b1s, xhH, f1, ty);   // f1 = elu
            YBAR();
            if (ty < 208)
                gemm_c1<208, S1, 1, 2>(g_W2t, g_b2s, f1, f2, ty);    // f2 = elu
            YBAR();
            if (ty < 192) {
                // heads: 3-way K-split {70,70,68}
                int p = ty >> 6, o = ty & 63;
                int k0 = p * 70, kn = (p == 2) ? 68 : 70;
                const float* wp = g_Wms + k0 * 64 + o;
                const float* xb = f2 + k0 * BT;
                unsigned long long acc[8];
#pragma unroll
                for (int q = 0; q < 8; q++) acc[q] = 0ull;
                for (int k = 0; k < kn; k += 2) {
                    float w0 = __ldg(wp + k * 64);
                    float w1 = __ldg(wp + (k + 1) * 64);
                    unsigned long long wd0 = splat2_(w0), wd1 = splat2_(w1);
                    const ulonglong2* x0 = reinterpret_cast<const ulonglong2*>(xb + k * BT);
                    const ulonglong2* x1 = reinterpret_cast<const ulonglong2*>(xb + (k + 1) * BT);
#pragma unroll
                    for (int q = 0; q < 4; q++) {
                        ulonglong2 a = x0[q], b = x1[q];
                        acc[2 * q]     = fma2_(wd0, a.x, acc[2 * q]);
                        acc[2 * q + 1] = fma2_(wd0, a.y, acc[2 * q + 1]);
                        acc[2 * q]     = fma2_(wd1, b.x, acc[2 * q]);
                        acc[2 * q + 1] = fma2_(wd1, b.y, acc[2 * q + 1]);
                    }
                }
                float v[16];
#pragma unroll
                for (int q = 0; q < 8; q++) { unpack2_(acc[q], v[2 * q], v[2 * q + 1]); }
                float4* dp = reinterpret_cast<float4*>(hp + p * 1024 + o * BT);
#pragma unroll
                for (int q = 0; q < 4; q++)
                    dp[q] = make_float4(v[4 * q], v[4 * q + 1], v[4 * q + 2], v[4 * q + 3]);
            }
            YBAR();
            // reduce head partials -> ms
            for (int idx = ty; idx < 1024; idx += 224) {
                int o = idx >> 4;
                float v = hp[idx] + hp[1024 + idx] + hp[2048 + idx] + g_bms[o];
                if (o < 32) ms[idx] = v;
                else        ms[idx] = __expf(fminf(fmaxf(v, -10.0f), 2.0f));
            }
            YBAR();
            // z(t) = mean + std*eps -> state
            for (int idx = ty; idx < Sn * BT; idx += 224)
                xh[idx] = ms[idx] + ms[512 + idx] * ep[idx];
        }
        __syncthreads();   // join

        // ---- P4: emit step t; stage t+1 ----
        emit_step(t, tid, NT);
        if (t + 1 < Hn) stage(t + 1, tid, NT);
        __syncthreads();
    }
}

// ---------- launch ----------
extern "C" void kernel_launch(void* const* d_in, const int* in_sizes, int n_in,
                              void* d_out, int out_size)
{
    const float* h0      = (const float*)d_in[0];
    const float* z0      = (const float*)d_in[1];
    const float* actions = (const float*)d_in[2];
    const float* eps_    = (const float*)d_in[3];
    const float* W_ih = (const float*)d_in[4];  const float* b_ih = (const float*)d_in[5];
    const float* W_hh = (const float*)d_in[6];  const float* b_hh = (const float*)d_in[7];
    const float* W1   = (const float*)d_in[8];  const float* b1   = (const float*)d_in[9];
    const float* W2   = (const float*)d_in[10]; const float* b2   = (const float*)d_in[11];
    const float* Wm   = (const float*)d_in[12]; const float* bm   = (const float*)d_in[13];
    const float* Ws   = (const float*)d_in[14]; const float* bs   = (const float*)d_in[15];
    float* out = (float*)d_out;

    cudaFuncSetAttribute(rssm_main, cudaFuncAttributeMaxDynamicSharedMemorySize, SMEMB);

    rssm_preproc<<<128, 256>>>(W_ih, b_ih, W_hh, b_hh, W1, b1, W2, b2, Wm, bm, Ws, bs);
    rssm_main<<<Bn / BT, NT, SMEMB>>>(h0, z0, actions, eps_, out);
}

// round 16
// speedup vs baseline: 1.1214x; 1.0942x over previous
#include <cuda_runtime.h>
#include <math.h>

#define Bn   2048
#define Hn   64
#define An   32
#define Sn   32
#define Dn   200
#define OUTC 296
#define BT   16
#define NT   512

#define SZ   640   // [64][640]:  ru_z(416) | i_n(208) | pad16
#define SH   624   // [208][624]: ru_h(416) | hn(208)
#define S1   208

// ---------- persistent transposed weights ----------
__device__ float g_Wz [64  * SZ];
__device__ float g_Wfh[208 * SH];
__device__ float g_W1t[208 * S1];
__device__ float g_W2t[208 * S1];
__device__ float g_Wms[208 * 64];
__device__ float g_bru[416];
__device__ float g_bin[208];
__device__ float g_bhn[208];
__device__ float g_b1s[208];
__device__ float g_b2s[208];
__device__ float g_bms[64];

// ---------- packed fp32x2 helpers ----------
__device__ __forceinline__ unsigned long long fma2_(unsigned long long a,
                                                    unsigned long long b,
                                                    unsigned long long c) {
    unsigned long long d;
    asm("fma.rn.f32x2 %0, %1, %2, %3;" : "=l"(d) : "l"(a), "l"(b), "l"(c));
    return d;
}
__device__ __forceinline__ unsigned long long splat2_(float w) {
    unsigned long long d;
    asm("mov.b64 %0, {%1, %1};" : "=l"(d) : "f"(w));
    return d;
}
__device__ __forceinline__ void unpack2_(unsigned long long v, float& lo, float& hi) {
    asm("mov.b64 {%0, %1}, %2;" : "=f"(lo), "=f"(hi) : "l"(v));
}
__device__ __forceinline__ float sigf_(float x) { return 1.0f / (1.0f + __expf(-x)); }
#define YBAR() asm volatile("bar.sync 1, 352;" ::: "memory")

// ---------- weight transpose / fuse ----------
__global__ void rssm_preproc(
    const float* __restrict__ W_ih, const float* __restrict__ b_ih,
    const float* __restrict__ W_hh, const float* __restrict__ b_hh,
    const float* __restrict__ W1,   const float* __restrict__ b1,
    const float* __restrict__ W2,   const float* __restrict__ b2,
    const float* __restrict__ Wm,   const float* __restrict__ bm,
    const float* __restrict__ Ws,   const float* __restrict__ bs)
{
    int i0 = blockIdx.x * blockDim.x + threadIdx.x;
    int stride = gridDim.x * blockDim.x;

    for (int idx = i0; idx < 64 * SZ; idx += stride) {
        int k = idx / SZ, o = idx % SZ;
        float v = 0.0f;
        if (o < 400) v = W_ih[o * 64 + k];
        else if (o >= 416 && o < 616) v = W_ih[(400 + o - 416) * 64 + k];
        g_Wz[idx] = v;
    }
    for (int idx = i0; idx < 208 * SH; idx += stride) {
        int k = idx / SH, o = idx % SH;
        float v = 0.0f;
        if (k < 200) {
            if (o < 400) v = W_hh[o * 200 + k];
            else if (o >= 416 && o < 616) v = W_hh[(400 + o - 416) * 200 + k];
        }
        g_Wfh[idx] = v;
    }
    for (int idx = i0; idx < 208 * S1; idx += stride) {
        int k = idx / S1, o = idx % S1;
        bool live = (k < 200) && (o < 200);
        g_W1t[idx] = live ? W1[o * 200 + k] : 0.0f;
        g_W2t[idx] = live ? W2[o * 200 + k] : 0.0f;
    }
    for (int idx = i0; idx < 208 * 64; idx += stride) {
        int k = idx / 64, o = idx % 64;
        float v = 0.0f;
        if (k < 200) v = (o < 32) ? Wm[o * 200 + k] : Ws[(o - 32) * 200 + k];
        g_Wms[idx] = v;
    }
    for (int idx = i0; idx < 416; idx += stride)
        g_bru[idx] = (idx < 400) ? (b_ih[idx] + b_hh[idx]) : 0.0f;
    for (int idx = i0; idx < 208; idx += stride) {
        bool live = (idx < 200);
        g_bin[idx] = live ? b_ih[400 + idx] : 0.0f;
        g_bhn[idx] = live ? b_hh[400 + idx] : 0.0f;
        g_b1s[idx] = live ? b1[idx] : 0.0f;
        g_b2s[idx] = live ? b2[idx] : 0.0f;
    }
    for (int idx = i0; idx < 64; idx += stride)
        g_bms[idx] = (idx < 32) ? bm[idx] : bs[idx - 32];
}

// ---------- gemmA: C=4 cols x 8 rows (RG=2), LDG.128 weights, depth-4 prefetch ----
// threads: NOUT/2. K % 8 == 0. BIAS opt. ACT: 0=none, 2=elu.
template<int K, int SR, int BIAS, int ACT>
__device__ __forceinline__ void gemmA(const float* __restrict__ Wt,
                                      const float* __restrict__ bias,
                                      const float* __restrict__ xT,
                                      float* __restrict__ outT, int t)
{
    const int cg = t >> 1, rg = t & 1;
    const float* wp = Wt + cg * 4;
    const float* xb = xT + rg * 8;

    unsigned long long acc[4][4];
#pragma unroll
    for (int ci = 0; ci < 4; ci++)
#pragma unroll
        for (int q = 0; q < 4; q++) acc[ci][q] = 0ull;

    auto LD = [&](float4* b, int k0) {
#pragma unroll
        for (int p = 0; p < 4; p++)
            b[p] = __ldg(reinterpret_cast<const float4*>(wp + (size_t)(k0 + p) * SR));
    };
    auto CP = [&](const float4* b, int k0) {
#pragma unroll
        for (int p = 0; p < 4; p++) {
            int k = k0 + p;
            ulonglong2 xa = *reinterpret_cast<const ulonglong2*>(xb + k * BT);
            ulonglong2 xc = *reinterpret_cast<const ulonglong2*>(xb + k * BT + 4);
            unsigned long long xv[4] = {xa.x, xa.y, xc.x, xc.y};
            float w[4] = {b[p].x, b[p].y, b[p].z, b[p].w};
#pragma unroll
            for (int ci = 0; ci < 4; ci++) {
                unsigned long long wd = splat2_(w[ci]);
#pragma unroll
                for (int q = 0; q < 4; q++)
                    acc[ci][q] = fma2_(wd, xv[q], acc[ci][q]);
            }
        }
    };

    float4 bufA[4], bufB[4];
    LD(bufA, 0);
    for (int k0 = 0; k0 < K; k0 += 8) {
        LD(bufB, k0 + 4);
        CP(bufA, k0);
        if (k0 + 8 < K) LD(bufA, k0 + 8);
        CP(bufB, k0 + 4);
    }

#pragma unroll
    for (int ci = 0; ci < 4; ci++) {
        int c = cg * 4 + ci;
        float bv = BIAS ? bias[c] : 0.0f;
        float v[8];
#pragma unroll
        for (int q = 0; q < 4; q++) {
            unpack2_(acc[ci][q], v[2 * q], v[2 * q + 1]);
            v[2 * q] += bv; v[2 * q + 1] += bv;
        }
        if (ACT == 2) {
#pragma unroll
            for (int r = 0; r < 8; r++) v[r] = v[r] > 0.0f ? v[r] : (__expf(v[r]) - 1.0f);
        }
        float* op = outT + c * BT + rg * 8;
        reinterpret_cast<float4*>(op)[0] = make_float4(v[0], v[1], v[2], v[3]);
        reinterpret_cast<float4*>(op)[1] = make_float4(v[4], v[5], v[6], v[7]);
    }
}

// ---------- gemmB: C=4 cols x 16 rows (RG=1), LDG.128 weights, depth-4 prefetch ---
// threads: NOUT/4. K % 8 == 0. Raw output.
template<int K, int SR>
__device__ __forceinline__ void gemmB(const float* __restrict__ Wt,
                                      const float* __restrict__ xT,
                                      float* __restrict__ outT, int cg)
{
    const float* wp = Wt + cg * 4;

    unsigned long long acc[4][8];
#pragma unroll
    for (int ci = 0; ci < 4; ci++)
#pragma unroll
        for (int q = 0; q < 8; q++) acc[ci][q] = 0ull;

    auto LD = [&](float4* b, int k0) {
#pragma unroll
        for (int p = 0; p < 4; p++)
            b[p] = __ldg(reinterpret_cast<const float4*>(wp + (size_t)(k0 + p) * SR));
    };
    auto CP = [&](const float4* b, int k0) {
#pragma unroll
        for (int p = 0; p < 4; p++) {
            int k = k0 + p;
            const ulonglong2* xp = reinterpret_cast<const ulonglong2*>(xT + k * BT);
            ulonglong2 x0 = xp[0], x1 = xp[1], x2 = xp[2], x3 = xp[3];
            unsigned long long xv[8] = {x0.x, x0.y, x1.x, x1.y, x2.x, x2.y, x3.x, x3.y};
            float w[4] = {b[p].x, b[p].y, b[p].z, b[p].w};
#pragma unroll
            for (int ci = 0; ci < 4; ci++) {
                unsigned long long wd = splat2_(w[ci]);
#pragma unroll
                for (int q = 0; q < 8; q++)
                    acc[ci][q] = fma2_(wd, xv[q], acc[ci][q]);
            }
        }
    };

    float4 bufA[4], bufB[4];
    LD(bufA, 0);
    for (int k0 = 0; k0 < K; k0 += 8) {
        LD(bufB, k0 + 4);
        CP(bufA, k0);
        if (k0 + 8 < K) LD(bufA, k0 + 8);
        CP(bufB, k0 + 4);
    }

#pragma unroll
    for (int ci = 0; ci < 4; ci++) {
        float* op = outT + (cg * 4 + ci) * BT;
#pragma unroll
        for (int q = 0; q < 4; q++) {
            float a0, a1, a2, a3;
            unpack2_(acc[ci][2 * q], a0, a1);
            unpack2_(acc[ci][2 * q + 1], a2, a3);
            reinterpret_cast<float4*>(op)[q] = make_float4(a0, a1, a2, a3);
        }
    }
}

// ---------- main rollout kernel ----------
extern __shared__ float smf[];

#define OXH  0                    // [272][16]: z 0..31, a 32..63, h 64..271 (pad 264..271)
#define OEP  (OXH + 272*16)       // [32][16] eps
#define OGZ  (OEP + 32*16)        // [624][16]: ru_z(416) | i_n(208)
#define OFH  (OGZ + 624*16)       // [624][16]: ru_h(416) | hn(208)
#define OF1  (OFH + 624*16)       // [208][16]
#define OF2  (OF1 + 208*16)       // [208][16]
#define OHP  (OF2 + 208*16)       // [3][64][16] head partials
#define OMS  (OHP + 3*64*16)      // [64][16] mean/std
#define SMEMF (OMS + 64*16)
#define SMEMB (SMEMF * 4)

__global__ void __launch_bounds__(NT, 1) rssm_main(
    const float* __restrict__ h0, const float* __restrict__ z0,
    const float* __restrict__ actions, const float* __restrict__ eps,
    float* __restrict__ out)
{
    float* xh  = smf + OXH;
    float* ep  = smf + OEP;
    float* gz  = smf + OGZ;
    float* fh  = smf + OFH;
    float* f1  = smf + OF1;
    float* f2  = smf + OF2;
    float* hp  = smf + OHP;
    float* ms  = smf + OMS;

    const int tid = threadIdx.x;
    const int b0  = blockIdx.x * BT;
    float* xhH = xh + 64 * BT;

    auto emit_step = [&](int tq, int i0, int istep) {
        for (int idx = i0; idx < OUTC * BT; idx += istep) {
            int r = idx / OUTC, c = idx - r * OUTC;
            float v;
            if (c < 200)      v = xhH[c * BT + r];
            else if (c < 232) v = xh[(c - 200) * BT + r];
            else              v = ms[(c - 232) * BT + r];
            out[((size_t)(b0 + r) * Hn + tq) * OUTC + c] = v;
        }
    };
    auto stage = [&](int tq, int i0, int istep) {
        for (int idx = i0; idx < An * BT; idx += istep) {
            int r = idx >> 5, c = idx & 31;
            size_t gbase = ((size_t)(b0 + r) * Hn + tq);
            xh[(32 + c) * BT + r] = actions[gbase * An + c];
            ep[c * BT + r]        = eps[gbase * Sn + c];
        }
    };

    // prologue: state, pads, stage(0)
    for (int idx = tid; idx < Dn * BT; idx += NT) {
        int f = idx >> 4, r = idx & 15;
        xhH[idx] = h0[(b0 + r) * Dn + f];
    }
    for (int idx = tid; idx < Sn * BT; idx += NT) {
        int f = idx >> 4, r = idx & 15;
        xh[idx] = z0[(b0 + r) * Sn + f];
    }
    for (int idx = tid; idx < 8 * BT; idx += NT) {
        xhH[200 * BT + idx] = 0.0f;
        f1[200 * BT + idx] = 0.0f;
        f2[200 * BT + idx] = 0.0f;
    }
    stage(0, tid, NT);
    __syncthreads();

    // prologue fused-h from h0
    if (tid < 156)
        gemmB<208, SH>(g_Wfh, xhH, fh, tid);
    __syncthreads();

    for (int t = 0; t < Hn; t++) {
        // ---- P1: fused z-GEMM on warps 0-9; emit(t-1) on warps 10-15 ----
        if (tid < 320) {
            if (tid < 312)
                gemmA<64, SZ, 0, 0>(g_Wz, nullptr, xh, gz, tid);
        } else if (t > 0) {
            emit_step(t - 1, tid - 320, NT - 320);
        }
        __syncthreads();

        // ---- P2: pointwise GRU update (all threads) ----
        for (int idx = tid; idx < Dn * BT; idx += NT) {
            int f = idx >> 4;
            float rr = sigf_(gz[idx] + fh[idx] + g_bru[f]);
            float uu = sigf_(gz[(200 + f) * BT + (idx & 15)] +
                             fh[(200 + f) * BT + (idx & 15)] + g_bru[200 + f]);
            float hn = fh[(416 + f) * BT + (idx & 15)] + g_bhn[f];
            float nn = tanhf(gz[(416 + f) * BT + (idx & 15)] + g_bin[f] + rr * hn);
            float hv = xhH[idx];
            xhH[idx] = (1.0f - uu) * nn + uu * hv;
        }
        __syncthreads();

        // ---- P3: X (warps 0-4) next-step fused-h; Y (warps 5-15) MLP chain ----
        if (tid < 160) {
            if (tid < 156)
                gemmB<208, SH>(g_Wfh, xhH, fh, tid);
        } else {
            int ty = tid - 160;   // 0..351
            if (ty < 104)
                gemmA<208, S1, 1, 2>(g_W1t, g_b1s, xhH, f1, ty);   // f1 = elu
            YBAR();
            if (ty < 104)
                gemmA<208, S1, 1, 2>(g_W2t, g_b2s, f1, f2, ty);    // f2 = elu
            YBAR();
            if (ty < 192) {
                int p = ty >> 6, o = ty & 63;
                int k0 = p * 70, kn = (p == 2) ? 68 : 70;
                const float* wp = g_Wms + k0 * 64 + o;
                const float* xb = f2 + k0 * BT;
                unsigned long long acc[8];
#pragma unroll
                for (int q = 0; q < 8; q++) acc[q] = 0ull;
                for (int k = 0; k < kn; k += 2) {
                    float w0 = __ldg(wp + k * 64);
                    float w1 = __ldg(wp + (k + 1) * 64);
                    unsigned long long wd0 = splat2_(w0), wd1 = splat2_(w1);
                    const ulonglong2* x0 = reinterpret_cast<const ulonglong2*>(xb + k * BT);
                    const ulonglong2* x1 = reinterpret_cast<const ulonglong2*>(xb + (k + 1) * BT);
#pragma unroll
                    for (int q = 0; q < 4; q++) {
                        ulonglong2 a = x0[q], b = x1[q];
                        acc[2 * q]     = fma2_(wd0, a.x, acc[2 * q]);
                        acc[2 * q + 1] = fma2_(wd0, a.y, acc[2 * q + 1]);
                        acc[2 * q]     = fma2_(wd1, b.x, acc[2 * q]);
                        acc[2 * q + 1] = fma2_(wd1, b.y, acc[2 * q + 1]);
                    }
                }
                float v[16];
#pragma unroll
                for (int q = 0; q < 8; q++) { unpack2_(acc[q], v[2 * q], v[2 * q + 1]); }
                float4* dp = reinterpret_cast<float4*>(hp + p * 1024 + o * BT);
#pragma unroll
                for (int q = 0; q < 4; q++)
                    dp[q] = make_float4(v[4 * q], v[4 * q + 1], v[4 * q + 2], v[4 * q + 3]);
            }
            YBAR();
            for (int idx = ty; idx < 1024; idx += 352) {
                int o = idx >> 4;
                float v = hp[idx] + hp[1024 + idx] + hp[2048 + idx] + g_bms[o];
                if (o < 32) ms[idx] = v;
                else        ms[idx] = __expf(fminf(fmaxf(v, -10.0f), 2.0f));
            }
            YBAR();
            for (int idx = ty; idx < Sn * BT; idx += 352)
                xh[idx] = ms[idx] + ms[512 + idx] * ep[idx];
        }
        __syncthreads();   // join

        // ---- P4: stage t+1 (all threads; 512 elems = 1 iter) ----
        if (t + 1 < Hn) stage(t + 1, tid, NT);
        __syncthreads();
    }

    emit_step(Hn - 1, tid, NT);
}

// ---------- launch ----------
extern "C" void kernel_launch(void* const* d_in, const int* in_sizes, int n_in,
                              void* d_out, int out_size)
{
    const float* h0      = (const float*)d_in[0];
    const float* z0      = (const float*)d_in[1];
    const float* actions = (const float*)d_in[2];
    const float* eps_    = (const float*)d_in[3];
    const float* W_ih = (const float*)d_in[4];  const float* b_ih = (const float*)d_in[5];
    const float* W_hh = (const float*)d_in[6];  const float* b_hh = (const float*)d_in[7];
    const float* W1   = (const float*)d_in[8];  const float* b1   = (const float*)d_in[9];
    const float* W2   = (const float*)d_in[10]; const float* b2   = (const float*)d_in[11];
    const float* Wm   = (const float*)d_in[12]; const float* bm   = (const float*)d_in[13];
    const float* Ws   = (const float*)d_in[14]; const float* bs   = (const float*)d_in[15];
    float* out = (float*)d_out;

    cudaFuncSetAttribute(rssm_main, cudaFuncAttributeMaxDynamicSharedMemorySize, SMEMB);

    rssm_preproc<<<128, 256>>>(W_ih, b_ih, W_hh, b_hh, W1, b1, W2, b2, Wm, bm, Ws, bs);
    rssm_main<<<Bn / BT, NT, SMEMB>>>(h0, z0, actions, eps_, out);
}